// round 5
// baseline (speedup 1.0000x reference)
#include <cuda_runtime.h>
#include <cstdint>

#define NTASKS 64
#define NROWS  2048
#define INSZ   512
#define OUTSZ  512
#define MT     64          // M rows per CTA tile
#define NTILE  128         // N cols per CTA
#define KT     64          // K per stage tile
#define THREADS 256

// SMEM stage layout (bytes). Rows padded +16B for conflict-free ldmatrix.
#define ASTRIDE_B 144      // 64 bf16 cols * 2 + 16 pad
#define BSTRIDE_B 272      // 128 bf16 cols * 2 + 16 pad
#define AH 0
#define AL 9216            // 64*144
#define BH 18432
#define BL 35840           // 18432 + 64*272
#define STAGE 53248        // 35840 + 17408
#define SMEM_TOTAL (2 * STAGE)   // 106496 B per CTA -> 2 CTAs/SM

__device__ int g_row_order[NROWS];
__device__ int g_task_off[NTASKS + 1];

// ---------------- helpers ----------------
__device__ __forceinline__ uint32_t smem_u32(const void* p) {
    uint32_t a;
    asm("{ .reg .u64 t; cvta.to.shared.u64 t, %1; cvt.u32.u64 %0, t; }" : "=r"(a) : "l"(p));
    return a;
}
__device__ __forceinline__ void sts128(uint32_t a, uint32_t x, uint32_t y, uint32_t z, uint32_t w) {
    asm volatile("st.shared.v4.b32 [%0], {%1,%2,%3,%4};"
                 :: "r"(a), "r"(x), "r"(y), "r"(z), "r"(w) : "memory");
}
__device__ __forceinline__ uint32_t hi2(float x0, float x1) {  // truncated bf16 pair
    uint32_t d;
    asm("prmt.b32 %0, %1, %2, 0x7632;" : "=r"(d)
        : "r"(__float_as_uint(x0)), "r"(__float_as_uint(x1)));
    return d;
}
__device__ __forceinline__ uint32_t lo2(float x0, float x1) {  // packed bf16 residuals
    unsigned long long x, h, l;
    asm("mov.b64 %0, {%1, %2};" : "=l"(x) : "r"(__float_as_uint(x0)), "r"(__float_as_uint(x1)));
    h = x & 0xFFFF0000FFFF0000ull;          // truncate both to bf16 (exact hi parts)
    h ^= 0x8000000080000000ull;             // negate both
    asm("add.rn.f32x2 %0, %1, %2;" : "=l"(l) : "l"(x), "l"(h));   // exact residuals
    uint32_t l0, l1, d;
    asm("mov.b64 {%0, %1}, %2;" : "=r"(l0), "=r"(l1) : "l"(l));
    asm("cvt.rn.bf16x2.f32 %0, %1, %2;" : "=r"(d)
        : "r"(l1), "r"(l0));  // note: cvt takes f32 regs; reinterpret
    return d;
}
__device__ __forceinline__ void ldm_x4(uint32_t* r, uint32_t a) {
    asm volatile("ldmatrix.sync.aligned.m8n8.x4.shared.b16 {%0,%1,%2,%3}, [%4];"
                 : "=r"(r[0]), "=r"(r[1]), "=r"(r[2]), "=r"(r[3]) : "r"(a));
}
__device__ __forceinline__ void ldm_x4t(uint32_t* r, uint32_t a) {
    asm volatile("ldmatrix.sync.aligned.m8n8.x4.trans.shared.b16 {%0,%1,%2,%3}, [%4];"
                 : "=r"(r[0]), "=r"(r[1]), "=r"(r[2]), "=r"(r[3]) : "r"(a));
}
__device__ __forceinline__ void mma16816(float* c, const uint32_t* a, const uint32_t* b) {
    asm volatile("mma.sync.aligned.m16n8k16.row.col.f32.bf16.bf16.f32 "
                 "{%0,%1,%2,%3}, {%4,%5,%6,%7}, {%8,%9}, {%0,%1,%2,%3};"
                 : "+f"(c[0]), "+f"(c[1]), "+f"(c[2]), "+f"(c[3])
                 : "r"(a[0]), "r"(a[1]), "r"(a[2]), "r"(a[3]), "r"(b[0]), "r"(b[1]));
}

// ---------------------------------------------------------------------------
// Kernel 1: counting sort by task. Warp-scan prefix (no serial loop).
// ---------------------------------------------------------------------------
__global__ void sort_rows_kernel(const void* __restrict__ task_ids_raw) {
    __shared__ int counts[NTASKS], scan[NTASKS], cursor[NTASKS];
    __shared__ int wtot, is64;
    const int tid = threadIdx.x;
    if (tid < NTASKS) counts[tid] = 0;
    if (tid == 0) is64 = 1;
    __syncthreads();
    const int* as32 = (const int*)task_ids_raw;
    int nz = 0;
    for (int i = tid; i < NROWS / 2; i += THREADS)
        if (as32[2 * i + 1] != 0) nz = 1;
    if (nz) atomicExch(&is64, 0);
    __syncthreads();
    const int wide = is64;
    for (int i = tid; i < NROWS; i += THREADS)
        atomicAdd(&counts[wide ? as32[2 * i] : as32[i]], 1);
    __syncthreads();
    if (tid < NTASKS) {
        const int lane = tid & 31;
        int s = counts[tid];
        #pragma unroll
        for (int d = 1; d < 32; d <<= 1) {
            int v = __shfl_up_sync(0xFFFFFFFF, s, d);
            if (lane >= d) s += v;
        }
        if (tid == 31) wtot = s;
        scan[tid] = s;
    }
    __syncthreads();
    if (tid < NTASKS) {
        int excl = scan[tid] + ((tid >= 32) ? wtot : 0) - counts[tid];
        cursor[tid] = excl;
        g_task_off[tid] = excl;
    }
    if (tid == 0) g_task_off[NTASKS] = NROWS;
    __syncthreads();
    for (int i = tid; i < NROWS; i += THREADS) {
        int t = wide ? as32[2 * i] : as32[i];
        g_row_order[atomicAdd(&cursor[t], 1)] = i;
    }
}

// ---------------------------------------------------------------------------
// Kernel 2: bf16 hi/lo split GEMM via ldmatrix + mma.sync.m16n8k16.
// grid = (4, 64), 256 threads, 2 CTAs/SM. CTA tile 64m x 128n, K dbl-buffered.
// ---------------------------------------------------------------------------
struct Pref { float4 pa[4], pb[8]; };

__global__ __launch_bounds__(THREADS, 2)
void task_gemm_mma(const float* __restrict__ X, const float* __restrict__ W,
                   float* __restrict__ Out) {
    extern __shared__ __align__(16) char smem[];
    const uint32_t sb = smem_u32(smem);

    const int t    = blockIdx.y;
    const int r0   = g_task_off[t];
    const int r1   = g_task_off[t + 1];
    if (r0 >= r1) return;
    const int col0 = blockIdx.x * NTILE;

    const int tid = threadIdx.x, lane = tid & 31, wid = tid >> 5;
    const int mload = tid >> 2;        // 0..63 : A row / B k-row for loading
    const int c4    = tid & 3;

    const float* __restrict__ Wt = W + (size_t)t * INSZ * OUTSZ + col0;

    // compute-role coords: 8 warps = 2m x 4n, warp tile 32m x 32n
    const int m0w = (wid & 1) * 32;
    const int n0w = (wid >> 1) * 32;
    const int lr  = lane & 15;
    const int lc8 = (lane >> 4) * 8;
    const int er  = lane >> 2;
    const int ec  = (lane & 3) * 2;

    for (int base = r0; base < r1; base += MT) {
        const int nrows = min(MT, r1 - base);
        const bool avalid = mload < nrows;
        const float* __restrict__ aptr =
            avalid ? (X + (size_t)g_row_order[base + mload] * INSZ) : X;

        Pref p;
        auto ldg_tile = [&](int kt) {
            if (avalid) {
                #pragma unroll
                for (int j = 0; j < 4; j++)
                    p.pa[j] = *(const float4*)(aptr + kt * KT + (c4 * 4 + j) * 4);
            }
            const float* br = Wt + (size_t)(kt * KT + mload) * OUTSZ;
            #pragma unroll
            for (int j = 0; j < 8; j++)
                p.pb[j] = *(const float4*)(br + (c4 * 8 + j) * 4);
        };
        auto sts_tile = [&](int s) {
            const uint32_t stg = sb + s * STAGE;
            float4 a[4];
            #pragma unroll
            for (int j = 0; j < 4; j++)
                a[j] = avalid ? p.pa[j] : make_float4(0.f, 0.f, 0.f, 0.f);
            const uint32_t ao = stg + mload * ASTRIDE_B + c4 * 32;
            #pragma unroll
            for (int g = 0; g < 2; g++) {
                sts128(ao + AH + g * 16,
                       hi2(a[2*g].x, a[2*g].y), hi2(a[2*g].z, a[2*g].w),
                       hi2(a[2*g+1].x, a[2*g+1].y), hi2(a[2*g+1].z, a[2*g+1].w));
                sts128(ao + AL + g * 16,
                       lo2(a[2*g].x, a[2*g].y), lo2(a[2*g].z, a[2*g].w),
                       lo2(a[2*g+1].x, a[2*g+1].y), lo2(a[2*g+1].z, a[2*g+1].w));
            }
            const uint32_t bo = stg + mload * BSTRIDE_B + c4 * 64;
            #pragma unroll
            for (int g = 0; g < 4; g++) {
                sts128(bo + BH + g * 16,
                       hi2(p.pb[2*g].x, p.pb[2*g].y), hi2(p.pb[2*g].z, p.pb[2*g].w),
                       hi2(p.pb[2*g+1].x, p.pb[2*g+1].y), hi2(p.pb[2*g+1].z, p.pb[2*g+1].w));
                sts128(bo + BL + g * 16,
                       lo2(p.pb[2*g].x, p.pb[2*g].y), lo2(p.pb[2*g].z, p.pb[2*g].w),
                       lo2(p.pb[2*g+1].x, p.pb[2*g+1].y), lo2(p.pb[2*g+1].z, p.pb[2*g+1].w));
            }
        };

        float acc[2][4][4];
        #pragma unroll
        for (int i = 0; i < 2; i++)
            #pragma unroll
            for (int j = 0; j < 4; j++)
                #pragma unroll
                for (int q = 0; q < 4; q++) acc[i][j][q] = 0.f;

        ldg_tile(0);
        sts_tile(0);
        __syncthreads();

        for (int kt = 0; kt < INSZ / KT; kt++) {
            if (kt < 7) ldg_tile(kt + 1);

            const uint32_t stg = sb + (kt & 1) * STAGE;
            #pragma unroll
            for (int ks = 0; ks < 4; ks++) {
                const int k0 = ks * 16;
                uint32_t ah[2][4], al[2][4], bh[2][4], bl[2][4];
                #pragma unroll
                for (int mt = 0; mt < 2; mt++) {
                    const uint32_t aoff =
                        stg + (m0w + mt * 16 + lr) * ASTRIDE_B + (k0 + lc8) * 2;
                    ldm_x4(ah[mt], aoff + AH);
                    ldm_x4(al[mt], aoff + AL);
                }
                #pragma unroll
                for (int nc = 0; nc < 2; nc++) {
                    const uint32_t boff =
                        stg + (k0 + lr) * BSTRIDE_B + (n0w + nc * 16 + lc8) * 2;
                    ldm_x4t(bh[nc], boff + BH);
                    ldm_x4t(bl[nc], boff + BL);
                }
                #pragma unroll
                for (int mt = 0; mt < 2; mt++)
                    #pragma unroll
                    for (int nc = 0; nc < 2; nc++)
                        #pragma unroll
                        for (int h = 0; h < 2; h++) {
                            const int nf = nc * 2 + h;
                            mma16816(acc[mt][nf], ah[mt], &bh[nc][h * 2]);
                            mma16816(acc[mt][nf], al[mt], &bh[nc][h * 2]);
                            mma16816(acc[mt][nf], ah[mt], &bl[nc][h * 2]);
                        }
            }
            if (kt < 7) sts_tile((kt + 1) & 1);
            __syncthreads();
        }

        // epilogue: C frag m16n8: {c0,c1}@(er, ec), {c2,c3}@(er+8, ec)
        #pragma unroll
        for (int mt = 0; mt < 2; mt++) {
            const int ml0 = m0w + mt * 16 + er;
            const int ml1 = ml0 + 8;
            const int o0 = (ml0 < nrows) ? g_row_order[base + ml0] : -1;
            const int o1 = (ml1 < nrows) ? g_row_order[base + ml1] : -1;
            #pragma unroll
            for (int nf = 0; nf < 4; nf++) {
                const int col = col0 + n0w + nf * 8 + ec;
                if (o0 >= 0)
                    *(float2*)(Out + (size_t)o0 * OUTSZ + col) =
                        make_float2(acc[mt][nf][0], acc[mt][nf][1]);
                if (o1 >= 0)
                    *(float2*)(Out + (size_t)o1 * OUTSZ + col) =
                        make_float2(acc[mt][nf][2], acc[mt][nf][3]);
            }
        }
    }
}

extern "C" void kernel_launch(void* const* d_in, const int* in_sizes, int n_in,
                              void* d_out, int out_size) {
    const float* X        = (const float*)d_in[0];   // [2048, 512] fp32
    const void*  task_ids = d_in[1];                 // [2048] int64 (or int32)
    const float* W        = (const float*)d_in[2];   // [64, 512, 512] fp32
    float*       Out      = (float*)d_out;           // [2048, 512] fp32

    cudaFuncSetAttribute(task_gemm_mma, cudaFuncAttributeMaxDynamicSharedMemorySize, SMEM_TOTAL);
    sort_rows_kernel<<<1, THREADS>>>(task_ids);
    dim3 grid(OUTSZ / NTILE, NTASKS);
    task_gemm_mma<<<grid, THREADS, SMEM_TOTAL>>>(X, W, Out);
}